// round 15
// baseline (speedup 1.0000x reference)
#include <cuda_runtime.h>
#include <cuda_fp16.h>
#include <cstdint>

#define D 128
#define MAXN 100000
#define BM 128
#define NT 512
#define BN_EPS 1e-5f

// ---------------- scratch (device globals; no runtime allocation) -----------
__device__ __align__(16) __half g_aggh[(size_t)MAXN * D];  // fp16 aggregated msgs
__device__ __align__(16) __half g_xh[(size_t)MAXN * D];    // fp16 copy of x
__device__ __align__(16) __half g_yh[(size_t)MAXN * D];    // fp16 pre-BN activations
__device__ float g_csrc[MAXN];
__device__ float g_cdst[MAXN];
__device__ int   g_odeg[MAXN];
__device__ int   g_ideg[MAXN];
__device__ __align__(16) float g_colsum[D];
__device__ __align__(16) float g_colsq[D];
__device__ __align__(16) float g_scale[D];
__device__ __align__(16) float g_shift[D];

__device__ __forceinline__ unsigned h2u(__half2 h) {
    return *reinterpret_cast<unsigned*>(&h);
}

// ---------------- prep: degree histograms + x -> fp16 cast (one launch) ------
__global__ void k_prep(const int* __restrict__ src, const int* __restrict__ dst, int E,
                       const float4* __restrict__ x4, int xChunks, int xBlocks) {
    if ((int)blockIdx.x < xBlocks) {
        int i = blockIdx.x * 256 + threadIdx.x;          // uint4 chunk (8 halves)
        if (i < xChunks) {
            float4 aL = __ldg(&x4[2 * i]);
            float4 aH = __ldg(&x4[2 * i + 1]);
            uint4 o;
            o.x = h2u(__floats2half2_rn(aL.x, aL.y));
            o.y = h2u(__floats2half2_rn(aL.z, aL.w));
            o.z = h2u(__floats2half2_rn(aH.x, aH.y));
            o.w = h2u(__floats2half2_rn(aH.z, aH.w));
            ((uint4*)g_xh)[i] = o;
        }
    } else {
        int e = ((int)blockIdx.x - xBlocks) * 256 + threadIdx.x;
        if (e < E) {
            atomicAdd(&g_odeg[src[e]], 1);
            atomicAdd(&g_ideg[dst[e]], 1);
        }
    }
}

// also zeroes the BN accumulators (saves two memset launches)
__global__ void k_cnorm(int N) {
    int i = blockIdx.x * blockDim.x + threadIdx.x;
    if (i < D) { g_colsum[i] = 0.f; g_colsq[i] = 0.f; }
    if (i < N) {
        g_csrc[i] = rsqrtf(fmaxf((float)g_odeg[i], 1.0f));
        g_cdst[i] = rsqrtf(fmaxf((float)g_ideg[i], 1.0f));
    }
}

// ---------------- edge aggregation: fp16 gather + fp16x2 vector reductions ---
__global__ __launch_bounds__(256) void k_aggregate(
    const int* __restrict__ src, const int* __restrict__ dst, int E) {
    int t = blockIdx.x * blockDim.x + threadIdx.x;
    int e = (t >> 5) * 8 + ((t & 31) >> 2);
    if (e >= E) return;
    int c = t & 3;
    int s = __ldg(&src[e]);
    int d = __ldg(&dst[e]);
    float cs = __ldg(&g_csrc[s]);
    const uint4* xb = (const uint4*)(g_xh + (size_t)s * D);
    uint4 u[4];
    u[0] = __ldg(xb + c);     u[1] = __ldg(xb + c + 4);
    u[2] = __ldg(xb + c + 8); u[3] = __ldg(xb + c + 12);
    __half* p = g_aggh + (size_t)d * D;
#pragma unroll
    for (int i = 0; i < 4; i++) {
        int ch = c + i * 4;
        unsigned w[4];
#pragma unroll
        for (int j = 0; j < 4; j++) {
            float2 f = __half22float2(*(__half2*)&((unsigned*)&u[i])[j]);
            w[j] = h2u(__floats2half2_rn(f.x * cs, f.y * cs));
        }
        asm volatile("red.global.add.noftz.v4.f16x2 [%0], {%1, %2, %3, %4};"
                     :: "l"(p + ch * 8), "r"(w[0]), "r"(w[1]), "r"(w[2]), "r"(w[3])
                     : "memory");
    }
}

// ---------------- fp16 tensor-core fused dual GEMM ---------------------------
#define MMA_F16(d, a, b0_, b1_) \
    asm volatile("mma.sync.aligned.m16n8k16.row.col.f32.f16.f16.f32 " \
        "{%0,%1,%2,%3},{%4,%5,%6,%7},{%8,%9},{%0,%1,%2,%3};" \
        : "+f"(d[0]), "+f"(d[1]), "+f"(d[2]), "+f"(d[3]) \
        : "r"(a[0]), "r"(a[1]), "r"(a[2]), "r"(a[3]), "r"(b0_), "r"(b1_))

// one 128-row fp16 tile stage via cp.async (16B chunks, swizzled), 512 threads
__device__ __forceinline__ void stage_load(unsigned* buf, const __half* __restrict__ srcb,
                                           int row0, int N, int tid) {
#pragma unroll
    for (int i = 0; i < 4; i++) {
        int idx = tid + i * NT;
        int row = idx >> 4, kq = idx & 15;
        int grow = row0 + row;
        unsigned daddr = (unsigned)__cvta_generic_to_shared(
            buf + row * 64 + ((kq * 4) ^ ((row & 7) * 4)));
        const uint4* s = (const uint4*)(srcb + (size_t)(grow < N ? grow : 0) * D) + kq;
        int sz = grow < N ? 16 : 0;
        asm volatile("cp.async.cg.shared.global [%0], [%1], 16, %2;"
                     :: "r"(daddr), "l"(s), "r"(sz));
    }
}

// MMA over one branch for the current 128-row fp16 stage. Warp tile m32 x n32.
// BR: 0 -> W (h branch), 1 -> Wr (res branch)
#define MMA_STAGE(BR)                                                              \
    _Pragma("unroll")                                                              \
    for (int jp = 0; jp < 8; jp++) {                                               \
        unsigned a[2][4];                                                          \
        int w0 = jp * 8 + tig;                                                     \
        _Pragma("unroll")                                                          \
        for (int mf = 0; mf < 2; mf++) {                                           \
            int row = mw * 32 + mf * 16 + gid;                                     \
            a[mf][0] = asb[row * 64 + (w0 ^ (gid * 4))];                           \
            a[mf][1] = asb[(row + 8) * 64 + (w0 ^ (gid * 4))];                     \
            a[mf][2] = asb[row * 64 + ((w0 + 4) ^ (gid * 4))];                     \
            a[mf][3] = asb[(row + 8) * 64 + ((w0 + 4) ^ (gid * 4))];               \
        }                                                                          \
        _Pragma("unroll")                                                          \
        for (int t = 0; t < 4; t++) {                                              \
            uint2 bf = ws2[(((nw * 2 + (BR)) * 4 + t) << 8) + jp * 32 + lane];     \
            MMA_F16(acc[0][t], a[0], bf.x, bf.y);                                  \
            MMA_F16(acc[1][t], a[1], bf.x, bf.y);                                  \
        }                                                                          \
    }

// Block: 512 thr = 16 warps = 4(m) x 4(n); warp tile m32 x n32; BM=128 tiles.
// Branches sequential per tile (single acc set); res branch stashed fp16.
// smem: ws 64KB + 2 x 32KB stages + 32KB stash = 160KB.
__global__ __launch_bounds__(NT, 1) void k_gemm_fp16(
    const float* __restrict__ W, const float* __restrict__ bb,
    const float* __restrict__ Wr, const float* __restrict__ brr,
    int N, int numTiles)
{
    extern __shared__ unsigned smem_u[];
    unsigned* ws    = smem_u;           // 16384 words = 64KB
    unsigned* as0   = smem_u + 16384;   //  8192 words = 32KB (128 rows fp16)
    unsigned* as1   = smem_u + 24576;   //  8192 words = 32KB
    unsigned* stash = smem_u + 32768;   //  8192 words = 32KB (128 x 64 half2)
    const uint2* ws2 = (const uint2*)ws;

    const int tid  = threadIdx.x;
    const int lane = tid & 31;
    const int wid  = tid >> 5;
    const int mw   = wid >> 2;     // 0..3 (m group of 32 rows)
    const int nw   = wid & 3;      // 0..3 (n group of 32 cols)
    const int tig  = lane & 3;
    const int gid  = lane >> 2;

    // ---- one-time: fragment-major packed W/Wr in fp16 (RNE, unbiased) ----
    for (int cell = tid; cell < 8192; cell += NT) {
        int l   = cell & 31;
        int ks  = (cell >> 5) & 7;
        int t   = (cell >> 8) & 3;
        int cbr = (cell >> 10) & 1;
        int cnw = (cell >> 11) & 3;
        const float* Wb = cbr ? Wr : W;
        int n = cnw * 32 + t * 8 + (l >> 2);
        int k = ks * 16 + (l & 3) * 2;
        uint2 v;
        v.x = h2u(__floats2half2_rn(__ldg(&Wb[(k    ) * D + n]),
                                    __ldg(&Wb[(k + 1) * D + n])));
        v.y = h2u(__floats2half2_rn(__ldg(&Wb[(k + 8) * D + n]),
                                    __ldg(&Wb[(k + 9) * D + n])));
        ((uint2*)ws)[cell] = v;
    }

    // biases for this thread's 8 output columns
    float b_[8], q_[8];
#pragma unroll
    for (int t = 0; t < 4; t++) {
        int col = nw * 32 + t * 8 + 2 * tig;
        b_[2 * t] = __ldg(&bb[col]);   b_[2 * t + 1] = __ldg(&bb[col + 1]);
        q_[2 * t] = __ldg(&brr[col]);  q_[2 * t + 1] = __ldg(&brr[col + 1]);
    }

    float ts[8], tq[8];
#pragma unroll
    for (int i = 0; i < 8; i++) { ts[i] = 0.f; tq[i] = 0.f; }

    const int nT = (numTiles > (int)blockIdx.x)
                 ? (numTiles - blockIdx.x + gridDim.x - 1) / gridDim.x : 0;
    const int totalS = nT * 2;

    // stash addressing: row stride 64 half2 words; col2 = nw*16 + t*4 + tig
    const int col2b = nw * 16 + tig;

    // prologue: stage x (res) then agg (h) of tile 0
    stage_load(as0, g_xh, blockIdx.x * BM, N, tid);
    asm volatile("cp.async.commit_group;");
    stage_load(as1, g_aggh, blockIdx.x * BM, N, tid);
    asm volatile("cp.async.commit_group;");

    for (int s = 0; s < totalS; s++) {
        const int br   = s & 1;   // 0: res (x@Wr), 1: h (agg@W)
        const int tile = blockIdx.x + (s >> 1) * gridDim.x;
        const int row0 = tile * BM;

        asm volatile("cp.async.wait_group 1;");
        __syncthreads();
        const unsigned* asb = br ? as1 : as0;

        float acc[2][4][4];
#pragma unroll
        for (int mf = 0; mf < 2; mf++)
#pragma unroll
            for (int t = 0; t < 4; t++)
#pragma unroll
                for (int r = 0; r < 4; r++) acc[mf][t][r] = 0.f;

        if (br == 0) { MMA_STAGE(1) } else { MMA_STAGE(0) }

        __syncthreads();  // all reads of asb done before overwrite

        int s2 = s + 2;
        if (s2 < totalS) {
            int t2 = blockIdx.x + (s2 >> 1) * gridDim.x;
            stage_load((s2 & 1) ? as1 : as0, (s2 & 1) ? g_aggh : g_xh, t2 * BM, N, tid);
        }
        asm volatile("cp.async.commit_group;");

        if (br == 0) {
            // stash relu(res + q) as fp16 (thread-private slots, no sync needed)
#pragma unroll
            for (int mf = 0; mf < 2; mf++) {
                int lrA = mw * 32 + mf * 16 + gid;
                int lrB = lrA + 8;
#pragma unroll
                for (int t = 0; t < 4; t++) {
                    int c2 = col2b + t * 4;
                    __half2 hA = __floats2half2_rn(
                        fmaxf(acc[mf][t][0] + q_[2 * t], 0.f),
                        fmaxf(acc[mf][t][1] + q_[2 * t + 1], 0.f));
                    __half2 hB = __floats2half2_rn(
                        fmaxf(acc[mf][t][2] + q_[2 * t], 0.f),
                        fmaxf(acc[mf][t][3] + q_[2 * t + 1], 0.f));
                    stash[lrA * 64 + (c2 ^ ((lrA & 7) * 4))] = *(unsigned*)&hA;
                    stash[lrB * 64 + (c2 ^ ((lrB & 7) * 4))] = *(unsigned*)&hB;
                }
            }
        } else {
            // epilogue: y = relu(h*cd + b) + stash, write fp16 y, BN sums
#pragma unroll
            for (int mf = 0; mf < 2; mf++) {
                int lrA = mw * 32 + mf * 16 + gid;
                int lrB = lrA + 8;
                int rA = row0 + lrA, rB = rA + 8;
                float cdA = (rA < N) ? __ldg(&g_cdst[rA]) : 0.f;
                float cdB = (rB < N) ? __ldg(&g_cdst[rB]) : 0.f;
#pragma unroll
                for (int t = 0; t < 4; t++) {
                    int col = nw * 32 + t * 8 + 2 * tig;
                    int c2 = col2b + t * 4;
                    unsigned sA = stash[lrA * 64 + (c2 ^ ((lrA & 7) * 4))];
                    unsigned sB = stash[lrB * 64 + (c2 ^ ((lrB & 7) * 4))];
                    float2 rsA = __half22float2(*(__half2*)&sA);
                    float2 rsB = __half22float2(*(__half2*)&sB);
                    if (rA < N) {
                        float v0 = fmaxf(acc[mf][t][0] * cdA + b_[2 * t], 0.f) + rsA.x;
                        float v1 = fmaxf(acc[mf][t][1] * cdA + b_[2 * t + 1], 0.f) + rsA.y;
                        *(__half2*)&g_yh[(size_t)rA * D + col] = __floats2half2_rn(v0, v1);
                        ts[2 * t] += v0; tq[2 * t] += v0 * v0;
                        ts[2 * t + 1] += v1; tq[2 * t + 1] += v1 * v1;
                    }
                    if (rB < N) {
                        float v2 = fmaxf(acc[mf][t][2] * cdB + b_[2 * t], 0.f) + rsB.x;
                        float v3 = fmaxf(acc[mf][t][3] * cdB + b_[2 * t + 1], 0.f) + rsB.y;
                        *(__half2*)&g_yh[(size_t)rB * D + col] = __floats2half2_rn(v2, v3);
                        ts[2 * t] += v2; tq[2 * t] += v2 * v2;
                        ts[2 * t + 1] += v3; tq[2 * t + 1] += v3 * v3;
                    }
                }
            }
        }
    }

    // ---- BN sums: lanes gid 0..7 hold identical column sets -> reduce ----
#pragma unroll
    for (int i = 0; i < 8; i++) {
#pragma unroll
        for (int m = 4; m <= 16; m <<= 1) {
            ts[i] += __shfl_xor_sync(0xffffffffu, ts[i], m);
            tq[i] += __shfl_xor_sync(0xffffffffu, tq[i], m);
        }
    }
    if (gid == 0) {
#pragma unroll
        for (int i = 0; i < 8; i++) {
            int col = nw * 32 + (i >> 1) * 8 + 2 * tig + (i & 1);
            atomicAdd(&g_colsum[col], ts[i]);
            atomicAdd(&g_colsq[col], tq[i]);
        }
    }
}

// ---------------- BN parameter fold + apply ----------------------------------
__global__ void k_bnparams(const float* __restrict__ gamma, const float* __restrict__ beta, float invN) {
    int j = threadIdx.x;
    float mean = g_colsum[j] * invN;
    float var = fmaxf(g_colsq[j] * invN - mean * mean, 0.f);
    float s = rsqrtf(var + BN_EPS) * __ldg(&gamma[j]);
    g_scale[j] = s;
    g_shift[j] = __ldg(&beta[j]) - mean * s;
}

// reads fp16 y (8 halves per thread), writes fp32 out
__global__ __launch_bounds__(256) void k_bnapply(float4* __restrict__ out4, int chunks) {
    int i = blockIdx.x * blockDim.x + threadIdx.x;
    if (i >= chunks) return;
    uint4 u = ((const uint4*)g_yh)[i];
    int c0 = (i & 15) * 8;
    float4 o0, o1;
    float2 p;
    p = __half22float2(*(__half2*)&u.x);
    o0.x = p.x * g_scale[c0    ] + g_shift[c0    ];
    o0.y = p.y * g_scale[c0 + 1] + g_shift[c0 + 1];
    p = __half22float2(*(__half2*)&u.y);
    o0.z = p.x * g_scale[c0 + 2] + g_shift[c0 + 2];
    o0.w = p.y * g_scale[c0 + 3] + g_shift[c0 + 3];
    p = __half22float2(*(__half2*)&u.z);
    o1.x = p.x * g_scale[c0 + 4] + g_shift[c0 + 4];
    o1.y = p.y * g_scale[c0 + 5] + g_shift[c0 + 5];
    p = __half22float2(*(__half2*)&u.w);
    o1.z = p.x * g_scale[c0 + 6] + g_shift[c0 + 6];
    o1.w = p.y * g_scale[c0 + 7] + g_shift[c0 + 7];
    out4[2 * i]     = o0;
    out4[2 * i + 1] = o1;
}

// ---------------- launch ------------------------------------------------------
extern "C" void kernel_launch(void* const* d_in, const int* in_sizes, int n_in,
                              void* d_out, int out_size) {
    const float* x     = (const float*)d_in[0];
    const float* W     = (const float*)d_in[1];
    const float* b     = (const float*)d_in[2];
    const float* Wr    = (const float*)d_in[3];
    const float* br    = (const float*)d_in[4];
    const float* gamma = (const float*)d_in[5];
    const float* beta  = (const float*)d_in[6];
    const int*   src   = (const int*)d_in[7];
    const int*   dst   = (const int*)d_in[8];

    const int N = in_sizes[0] / D;
    const int E = in_sizes[7];

    void *p_aggh, *p_odeg, *p_ideg;
    cudaGetSymbolAddress(&p_aggh, g_aggh);
    cudaGetSymbolAddress(&p_odeg, g_odeg);
    cudaGetSymbolAddress(&p_ideg, g_ideg);

    cudaMemsetAsync(p_aggh, 0, (size_t)N * D * sizeof(__half));
    cudaMemsetAsync(p_odeg, 0, (size_t)N * sizeof(int));
    cudaMemsetAsync(p_ideg, 0, (size_t)N * sizeof(int));

    {
        int xChunks = N * (D / 8);
        int xBlocks = (xChunks + 255) / 256;
        int eBlocks = (E + 255) / 256;
        k_prep<<<xBlocks + eBlocks, 256>>>(src, dst, E, (const float4*)x, xChunks, xBlocks);
    }
    k_cnorm<<<(N + 255) / 256, 256>>>(N);

    {
        int blocks = (E + 63) / 64;
        k_aggregate<<<blocks, 256>>>(src, dst, E);
    }

    {
        const int smemBytes = 40960 * (int)sizeof(unsigned);  // 160 KB
        cudaFuncSetAttribute(k_gemm_fp16, cudaFuncAttributeMaxDynamicSharedMemorySize, smemBytes);
        int numTiles = (N + BM - 1) / BM;
        int grid = numTiles < 152 ? numTiles : 152;
        k_gemm_fp16<<<grid, NT, smemBytes>>>(W, b, Wr, br, N, numTiles);
    }

    k_bnparams<<<1, D>>>(gamma, beta, 1.0f / (float)N);
    {
        int chunks = N * (D / 8);
        k_bnapply<<<(chunks + 255) / 256, 256>>>((float4*)d_out, chunks);
    }
}

// round 16
// speedup vs baseline: 1.0396x; 1.0396x over previous
#include <cuda_runtime.h>
#include <cuda_fp16.h>
#include <cstdint>

#define D 128
#define MAXN 100000
#define BM 64
#define BN_EPS 1e-5f

// ---------------- scratch (device globals; no runtime allocation) -----------
__device__ __align__(16) __half g_aggh[(size_t)MAXN * D];  // fp16 aggregated msgs
__device__ __align__(16) __half g_xh[(size_t)MAXN * D];    // fp16 copy of x
__device__ __align__(16) __half g_yh[(size_t)MAXN * D];    // fp16 pre-BN activations
__device__ float g_csrc[MAXN];
__device__ float g_cdst[MAXN];
__device__ int   g_odeg[MAXN];
__device__ int   g_ideg[MAXN];
__device__ __align__(16) float g_colsum[D];
__device__ __align__(16) float g_colsq[D];
__device__ __align__(16) float g_scale[D];
__device__ __align__(16) float g_shift[D];

__device__ __forceinline__ unsigned h2u(__half2 h) {
    return *reinterpret_cast<unsigned*>(&h);
}

// ---------------- prep: degree histograms + x -> fp16 cast (one launch) ------
__global__ void k_prep(const int* __restrict__ src, const int* __restrict__ dst, int E,
                       const float4* __restrict__ x4, int xChunks, int xBlocks) {
    if ((int)blockIdx.x < xBlocks) {
        int i = blockIdx.x * 256 + threadIdx.x;          // uint4 chunk (8 halves)
        if (i < xChunks) {
            float4 aL = __ldg(&x4[2 * i]);
            float4 aH = __ldg(&x4[2 * i + 1]);
            uint4 o;
            o.x = h2u(__floats2half2_rn(aL.x, aL.y));
            o.y = h2u(__floats2half2_rn(aL.z, aL.w));
            o.z = h2u(__floats2half2_rn(aH.x, aH.y));
            o.w = h2u(__floats2half2_rn(aH.z, aH.w));
            ((uint4*)g_xh)[i] = o;
        }
    } else {
        int e = ((int)blockIdx.x - xBlocks) * 256 + threadIdx.x;
        if (e < E) {
            atomicAdd(&g_odeg[src[e]], 1);
            atomicAdd(&g_ideg[dst[e]], 1);
        }
    }
}

// also zeroes the BN accumulators (saves two memset launches)
__global__ void k_cnorm(int N) {
    int i = blockIdx.x * blockDim.x + threadIdx.x;
    if (i < D) { g_colsum[i] = 0.f; g_colsq[i] = 0.f; }
    if (i < N) {
        g_csrc[i] = rsqrtf(fmaxf((float)g_odeg[i], 1.0f));
        g_cdst[i] = rsqrtf(fmaxf((float)g_ideg[i], 1.0f));
    }
}

// ---------------- edge aggregation: fp16 gather + fp16x2 vector reductions ---
__global__ __launch_bounds__(256) void k_aggregate(
    const int* __restrict__ src, const int* __restrict__ dst, int E) {
    int t = blockIdx.x * blockDim.x + threadIdx.x;
    int e = (t >> 5) * 8 + ((t & 31) >> 2);
    if (e >= E) return;
    int c = t & 3;
    int s = __ldg(&src[e]);
    int d = __ldg(&dst[e]);
    float cs = __ldg(&g_csrc[s]);
    const uint4* xb = (const uint4*)(g_xh + (size_t)s * D);
    uint4 u[4];
    u[0] = __ldg(xb + c);     u[1] = __ldg(xb + c + 4);
    u[2] = __ldg(xb + c + 8); u[3] = __ldg(xb + c + 12);
    __half* p = g_aggh + (size_t)d * D;
#pragma unroll
    for (int i = 0; i < 4; i++) {
        int ch = c + i * 4;
        unsigned w[4];
#pragma unroll
        for (int j = 0; j < 4; j++) {
            float2 f = __half22float2(*(__half2*)&((unsigned*)&u[i])[j]);
            w[j] = h2u(__floats2half2_rn(f.x * cs, f.y * cs));
        }
        asm volatile("red.global.add.noftz.v4.f16x2 [%0], {%1, %2, %3, %4};"
                     :: "l"(p + ch * 8), "r"(w[0]), "r"(w[1]), "r"(w[2]), "r"(w[3])
                     : "memory");
    }
}

// ---------------- fp16 tensor-core fused dual GEMM ---------------------------
#define MMA_F16(d, a, b0_, b1_) \
    asm volatile("mma.sync.aligned.m16n8k16.row.col.f32.f16.f16.f32 " \
        "{%0,%1,%2,%3},{%4,%5,%6,%7},{%8,%9},{%0,%1,%2,%3};" \
        : "+f"(d[0]), "+f"(d[1]), "+f"(d[2]), "+f"(d[3]) \
        : "r"(a[0]), "r"(a[1]), "r"(a[2]), "r"(a[3]), "r"(b0_), "r"(b1_))

// one 64-row fp16 tile stage via cp.async (16B chunks, swizzled)
__device__ __forceinline__ void stage_load(unsigned* buf, const __half* __restrict__ srcb,
                                           int row0, int N, int tid) {
#pragma unroll
    for (int i = 0; i < 4; i++) {
        int idx = tid + i * 256;
        int row = idx >> 4, kq = idx & 15;
        int grow = row0 + row;
        unsigned daddr = (unsigned)__cvta_generic_to_shared(
            buf + row * 64 + ((kq * 4) ^ ((row & 7) * 4)));
        const uint4* s = (const uint4*)(srcb + (size_t)(grow < N ? grow : 0) * D) + kq;
        int sz = grow < N ? 16 : 0;
        asm volatile("cp.async.cg.shared.global [%0], [%1], 16, %2;"
                     :: "r"(daddr), "l"(s), "r"(sz));
    }
}

// MMA over one branch for the current 64-row fp16 stage. Warp tile m32 x n32.
#define MMA_STAGE(ACC, BR)                                                         \
    _Pragma("unroll")                                                              \
    for (int jp = 0; jp < 8; jp++) {                                               \
        unsigned a[2][4];                                                          \
        int w0 = jp * 8 + tig;                                                     \
        _Pragma("unroll")                                                          \
        for (int mf = 0; mf < 2; mf++) {                                           \
            int row = mw * 32 + mf * 16 + gid;                                     \
            a[mf][0] = asb[row * 64 + (w0 ^ (gid * 4))];                           \
            a[mf][1] = asb[(row + 8) * 64 + (w0 ^ (gid * 4))];                     \
            a[mf][2] = asb[row * 64 + ((w0 + 4) ^ (gid * 4))];                     \
            a[mf][3] = asb[(row + 8) * 64 + ((w0 + 4) ^ (gid * 4))];               \
        }                                                                          \
        _Pragma("unroll")                                                          \
        for (int t = 0; t < 4; t++) {                                              \
            uint2 bf = ws2[(((nw * 2 + (BR)) * 4 + t) << 8) + jp * 32 + lane];     \
            MMA_F16(ACC[0][t], a[0], bf.x, bf.y);                                  \
            MMA_F16(ACC[1][t], a[1], bf.x, bf.y);                                  \
        }                                                                          \
    }

// Block: 256 thr = 8 warps = 2(m) x 4(n); warp tile m32 x n32, both branches.
// 2 blocks/SM (regs capped at 128; biases live in smem).
// smem: ws 64KB + 2 x 16KB fp16 A stages + 1KB biases = 97KB per block.
__global__ __launch_bounds__(256, 2) void k_gemm_fp16(
    const float* __restrict__ W, const float* __restrict__ bb,
    const float* __restrict__ Wr, const float* __restrict__ brr,
    int N, int numTiles)
{
    extern __shared__ unsigned smem_u[];
    unsigned* ws  = smem_u;           // 16384 words = 64KB
    unsigned* as0 = smem_u + 16384;   //  4096 words = 16KB (64 rows fp16)
    unsigned* as1 = smem_u + 20480;   //  4096 words = 16KB
    float* bsm    = (float*)(smem_u + 24576);   // 128 floats
    float* qsm    = bsm + 128;                  // 128 floats
    const uint2* ws2 = (const uint2*)ws;

    const int tid  = threadIdx.x;
    const int lane = tid & 31;
    const int wid  = tid >> 5;
    const int mw   = wid >> 2;     // 0..1 (m group of 32 rows)
    const int nw   = wid & 3;      // 0..3 (n group of 32 cols)
    const int tig  = lane & 3;
    const int gid  = lane >> 2;

    // ---- one-time: fragment-major packed W/Wr in fp16 (RNE, unbiased) ----
    for (int cell = tid; cell < 8192; cell += 256) {
        int l   = cell & 31;
        int ks  = (cell >> 5) & 7;
        int t   = (cell >> 8) & 3;
        int cbr = (cell >> 10) & 1;
        int cnw = (cell >> 11) & 3;
        const float* Wb = cbr ? Wr : W;
        int n = cnw * 32 + t * 8 + (l >> 2);
        int k = ks * 16 + (l & 3) * 2;
        uint2 v;
        v.x = h2u(__floats2half2_rn(__ldg(&Wb[(k    ) * D + n]),
                                    __ldg(&Wb[(k + 1) * D + n])));
        v.y = h2u(__floats2half2_rn(__ldg(&Wb[(k + 8) * D + n]),
                                    __ldg(&Wb[(k + 9) * D + n])));
        ((uint2*)ws)[cell] = v;
    }
    if (tid < 128) { bsm[tid] = __ldg(&bb[tid]); qsm[tid] = __ldg(&brr[tid]); }

    float ts[8], tq[8];
#pragma unroll
    for (int i = 0; i < 8; i++) { ts[i] = 0.f; tq[i] = 0.f; }

    const int nT = (numTiles > (int)blockIdx.x)
                 ? (numTiles - blockIdx.x + gridDim.x - 1) / gridDim.x : 0;
    const int totalS = nT * 2;

    // prologue: stages 0 (agg of tile0) and 1 (xh of tile0)
    stage_load(as0, g_aggh, blockIdx.x * BM, N, tid);
    asm volatile("cp.async.commit_group;");
    stage_load(as1, g_xh, blockIdx.x * BM, N, tid);
    asm volatile("cp.async.commit_group;");

    float acc0[2][4][4], acc1[2][4][4];

    for (int s = 0; s < totalS; s++) {
        const int br   = s & 1;
        const int tile = blockIdx.x + (s >> 1) * gridDim.x;
        const int row0 = tile * BM;

        asm volatile("cp.async.wait_group 1;");
        __syncthreads();
        const unsigned* asb = br ? as1 : as0;

        if (br == 0) {
#pragma unroll
            for (int mf = 0; mf < 2; mf++)
#pragma unroll
                for (int t = 0; t < 4; t++)
#pragma unroll
                    for (int r = 0; r < 4; r++) { acc0[mf][t][r] = 0.f; acc1[mf][t][r] = 0.f; }
            MMA_STAGE(acc0, 0)
        } else {
            MMA_STAGE(acc1, 1)
        }

        __syncthreads();  // all reads of asb done before overwrite

        int s2 = s + 2;
        if (s2 < totalS) {
            int t2 = blockIdx.x + (s2 >> 1) * gridDim.x;
            stage_load((s2 & 1) ? as1 : as0, (s2 & 1) ? g_xh : g_aggh, t2 * BM, N, tid);
        }
        asm volatile("cp.async.commit_group;");

        if (br == 1) {
            // epilogue: y = relu(h*cd + b) + relu(res + q), write fp16 y, BN sums
#pragma unroll
            for (int mf = 0; mf < 2; mf++) {
                int rA = row0 + mw * 32 + mf * 16 + gid;
                int rB = rA + 8;
                float cdA = (rA < N) ? __ldg(&g_cdst[rA]) : 0.f;
                float cdB = (rB < N) ? __ldg(&g_cdst[rB]) : 0.f;
#pragma unroll
                for (int t = 0; t < 4; t++) {
                    int col = nw * 32 + t * 8 + 2 * tig;
                    float2 b2 = *(float2*)&bsm[col];
                    float2 q2 = *(float2*)&qsm[col];
                    if (rA < N) {
                        float v0 = fmaxf(acc0[mf][t][0] * cdA + b2.x, 0.f)
                                 + fmaxf(acc1[mf][t][0] + q2.x, 0.f);
                        float v1 = fmaxf(acc0[mf][t][1] * cdA + b2.y, 0.f)
                                 + fmaxf(acc1[mf][t][1] + q2.y, 0.f);
                        *(__half2*)&g_yh[(size_t)rA * D + col] = __floats2half2_rn(v0, v1);
                        ts[2 * t] += v0; tq[2 * t] += v0 * v0;
                        ts[2 * t + 1] += v1; tq[2 * t + 1] += v1 * v1;
                    }
                    if (rB < N) {
                        float v2 = fmaxf(acc0[mf][t][2] * cdB + b2.x, 0.f)
                                 + fmaxf(acc1[mf][t][2] + q2.x, 0.f);
                        float v3 = fmaxf(acc0[mf][t][3] * cdB + b2.y, 0.f)
                                 + fmaxf(acc1[mf][t][3] + q2.y, 0.f);
                        *(__half2*)&g_yh[(size_t)rB * D + col] = __floats2half2_rn(v2, v3);
                        ts[2 * t] += v2; tq[2 * t] += v2 * v2;
                        ts[2 * t + 1] += v3; tq[2 * t + 1] += v3 * v3;
                    }
                }
            }
        }
    }

    // ---- BN sums: lanes gid 0..7 hold identical column sets -> reduce ----
#pragma unroll
    for (int i = 0; i < 8; i++) {
#pragma unroll
        for (int m = 4; m <= 16; m <<= 1) {
            ts[i] += __shfl_xor_sync(0xffffffffu, ts[i], m);
            tq[i] += __shfl_xor_sync(0xffffffffu, tq[i], m);
        }
    }
    if (gid == 0) {
#pragma unroll
        for (int i = 0; i < 8; i++) {
            int col = nw * 32 + (i >> 1) * 8 + 2 * tig + (i & 1);
            atomicAdd(&g_colsum[col], ts[i]);
            atomicAdd(&g_colsq[col], tq[i]);
        }
    }
}

// ---------------- BN parameter fold + apply ----------------------------------
__global__ void k_bnparams(const float* __restrict__ gamma, const float* __restrict__ beta, float invN) {
    int j = threadIdx.x;
    float mean = g_colsum[j] * invN;
    float var = fmaxf(g_colsq[j] * invN - mean * mean, 0.f);
    float s = rsqrtf(var + BN_EPS) * __ldg(&gamma[j]);
    g_scale[j] = s;
    g_shift[j] = __ldg(&beta[j]) - mean * s;
}

// reads fp16 y (8 halves per thread), writes fp32 out
__global__ __launch_bounds__(256) void k_bnapply(float4* __restrict__ out4, int chunks) {
    int i = blockIdx.x * blockDim.x + threadIdx.x;
    if (i >= chunks) return;
    uint4 u = ((const uint4*)g_yh)[i];
    int c0 = (i & 15) * 8;
    float4 o0, o1;
    float2 p;
    p = __half22float2(*(__half2*)&u.x);
    o0.x = p.x * g_scale[c0    ] + g_shift[c0    ];
    o0.y = p.y * g_scale[c0 + 1] + g_shift[c0 + 1];
    p = __half22float2(*(__half2*)&u.y);
    o0.z = p.x * g_scale[c0 + 2] + g_shift[c0 + 2];
    o0.w = p.y * g_scale[c0 + 3] + g_shift[c0 + 3];
    p = __half22float2(*(__half2*)&u.z);
    o1.x = p.x * g_scale[c0 + 4] + g_shift[c0 + 4];
    o1.y = p.y * g_scale[c0 + 5] + g_shift[c0 + 5];
    p = __half22float2(*(__half2*)&u.w);
    o1.z = p.x * g_scale[c0 + 6] + g_shift[c0 + 6];
    o1.w = p.y * g_scale[c0 + 7] + g_shift[c0 + 7];
    out4[2 * i]     = o0;
    out4[2 * i + 1] = o1;
}

// ---------------- launch ------------------------------------------------------
extern "C" void kernel_launch(void* const* d_in, const int* in_sizes, int n_in,
                              void* d_out, int out_size) {
    const float* x     = (const float*)d_in[0];
    const float* W     = (const float*)d_in[1];
    const float* b     = (const float*)d_in[2];
    const float* Wr    = (const float*)d_in[3];
    const float* br    = (const float*)d_in[4];
    const float* gamma = (const float*)d_in[5];
    const float* beta  = (const float*)d_in[6];
    const int*   src   = (const int*)d_in[7];
    const int*   dst   = (const int*)d_in[8];

    const int N = in_sizes[0] / D;
    const int E = in_sizes[7];

    void *p_aggh, *p_odeg, *p_ideg;
    cudaGetSymbolAddress(&p_aggh, g_aggh);
    cudaGetSymbolAddress(&p_odeg, g_odeg);
    cudaGetSymbolAddress(&p_ideg, g_ideg);

    cudaMemsetAsync(p_aggh, 0, (size_t)N * D * sizeof(__half));
    cudaMemsetAsync(p_odeg, 0, (size_t)N * sizeof(int));
    cudaMemsetAsync(p_ideg, 0, (size_t)N * sizeof(int));

    {
        int xChunks = N * (D / 8);
        int xBlocks = (xChunks + 255) / 256;
        int eBlocks = (E + 255) / 256;
        k_prep<<<xBlocks + eBlocks, 256>>>(src, dst, E, (const float4*)x, xChunks, xBlocks);
    }
    k_cnorm<<<(N + 255) / 256, 256>>>(N);

    {
        int blocks = (E + 63) / 64;
        k_aggregate<<<blocks, 256>>>(src, dst, E);
    }

    {
        const int smemBytes = 24832 * (int)sizeof(unsigned);  // 97 KB
        cudaFuncSetAttribute(k_gemm_fp16, cudaFuncAttributeMaxDynamicSharedMemorySize, smemBytes);
        int numTiles = (N + BM - 1) / BM;
        int grid = numTiles < 304 ? numTiles : 304;   // 2 blocks per SM
        k_gemm_fp16<<<grid, 256, smemBytes>>>(W, b, Wr, br, N, numTiles);
    }

    k_bnparams<<<1, D>>>(gamma, beta, 1.0f / (float)N);
    {
        int chunks = N * (D / 8);
        k_bnapply<<<(chunks + 255) / 256, 256>>>((float4*)d_out, chunks);
    }
}

// round 17
// speedup vs baseline: 1.0597x; 1.0193x over previous
#include <cuda_runtime.h>
#include <cuda_fp16.h>
#include <cstdint>

#define D 128
#define MAXN 100000
#define MAXE 400000
#define BM 64
#define BN_EPS 1e-5f

// ---------------- scratch (device globals; no runtime allocation) -----------
__device__ __align__(16) __half g_aggh[(size_t)MAXN * D];  // fp16 aggregated msgs
__device__ __align__(16) __half g_xh[(size_t)MAXN * D];    // fp16 copy of x
__device__ __align__(16) __half g_yh[(size_t)MAXN * D];    // fp16 pre-BN activations
__device__ __align__(16) uint2 g_wsp[8192];                // packed fp16 W/Wr fragments
__device__ float g_csrc[MAXN];
__device__ float g_cdst[MAXN];
__device__ int   g_odeg[MAXN];
__device__ int   g_ideg[MAXN];
__device__ int   g_off[MAXN];     // CSR start offsets (bucket order arbitrary)
__device__ int   g_fill[MAXN];    // scatter cursors
__device__ int   g_elist[MAXE];   // src ids bucketed by dst
__device__ int   g_ecnt;          // global offset counter
__device__ __align__(16) float g_colsum[D];
__device__ __align__(16) float g_colsq[D];
__device__ __align__(16) float g_scale[D];
__device__ __align__(16) float g_shift[D];

__device__ __forceinline__ unsigned h2u(__half2 h) {
    return *reinterpret_cast<unsigned*>(&h);
}

// ---------------- prep: x->fp16 cast + degree histograms + weight pack -------
__global__ void k_prep(const int* __restrict__ src, const int* __restrict__ dst, int E,
                       const float4* __restrict__ x4, int xChunks, int xBlocks, int eBlocks,
                       const float* __restrict__ W, const float* __restrict__ Wr) {
    int bid = blockIdx.x;
    if (bid < xBlocks) {
        int i = bid * 256 + threadIdx.x;                 // uint4 chunk (8 halves)
        if (i < xChunks) {
            float4 aL = __ldg(&x4[2 * i]);
            float4 aH = __ldg(&x4[2 * i + 1]);
            uint4 o;
            o.x = h2u(__floats2half2_rn(aL.x, aL.y));
            o.y = h2u(__floats2half2_rn(aL.z, aL.w));
            o.z = h2u(__floats2half2_rn(aH.x, aH.y));
            o.w = h2u(__floats2half2_rn(aH.z, aH.w));
            ((uint4*)g_xh)[i] = o;
        }
    } else if (bid < xBlocks + eBlocks) {
        int e = (bid - xBlocks) * 256 + threadIdx.x;
        if (e < E) {
            atomicAdd(&g_odeg[src[e]], 1);
            atomicAdd(&g_ideg[dst[e]], 1);
        }
    } else {
        // fragment-major fp16 weight pack (8192 uint2 cells)
        int cell = (bid - xBlocks - eBlocks) * 256 + threadIdx.x;
        if (cell < 8192) {
            int l   = cell & 31;
            int ks  = (cell >> 5) & 7;
            int t   = (cell >> 8) & 3;
            int cbr = (cell >> 10) & 1;
            int cnw = (cell >> 11) & 3;
            const float* Wb = cbr ? Wr : W;
            int n = cnw * 32 + t * 8 + (l >> 2);
            int k = ks * 16 + (l & 3) * 2;
            uint2 v;
            v.x = h2u(__floats2half2_rn(__ldg(&Wb[(k    ) * D + n]),
                                        __ldg(&Wb[(k + 1) * D + n])));
            v.y = h2u(__floats2half2_rn(__ldg(&Wb[(k + 8) * D + n]),
                                        __ldg(&Wb[(k + 9) * D + n])));
            g_wsp[cell] = v;
        }
    }
}

// also zeroes the BN accumulators
__global__ void k_cnorm(int N) {
    int i = blockIdx.x * blockDim.x + threadIdx.x;
    if (i < D) { g_colsum[i] = 0.f; g_colsq[i] = 0.f; }
    if (i < N) {
        g_csrc[i] = rsqrtf(fmaxf((float)g_odeg[i], 1.0f));
        g_cdst[i] = rsqrtf(fmaxf((float)g_ideg[i], 1.0f));
    }
}

// ---------------- CSR build: offsets via block scan + one global atomic ------
__global__ __launch_bounds__(256) void k_offsets(int N) {
    __shared__ int wsum[8];
    __shared__ int bbase;
    int i = blockIdx.x * 256 + threadIdx.x;
    int lane = threadIdx.x & 31, wid = threadIdx.x >> 5;
    int deg = (i < N) ? g_ideg[i] : 0;
    int v = deg;
#pragma unroll
    for (int o = 1; o < 32; o <<= 1) {
        int t = __shfl_up_sync(0xffffffffu, v, o);
        if (lane >= o) v += t;
    }
    if (lane == 31) wsum[wid] = v;
    __syncthreads();
    if (wid == 0) {
        int s = (lane < 8) ? wsum[lane] : 0;
#pragma unroll
        for (int o = 1; o < 8; o <<= 1) {
            int t = __shfl_up_sync(0xffffffffu, s, o);
            if (lane >= o) s += t;
        }
        if (lane < 8) wsum[lane] = s;
        if (lane == 7) bbase = atomicAdd(&g_ecnt, s);
    }
    __syncthreads();
    if (i < N) {
        int o = bbase + (wid ? wsum[wid - 1] : 0) + v - deg;
        g_off[i] = o;
        g_fill[i] = o;
    }
}

__global__ void k_binedges(const int* __restrict__ src, const int* __restrict__ dst, int E) {
    int e = blockIdx.x * blockDim.x + threadIdx.x;
    if (e < E) {
        int slot = atomicAdd(&g_fill[dst[e]], 1);
        g_elist[slot] = src[e];
    }
}

// ---------------- aggregation: warp per node, fp32 accumulate, no atomics ----
__global__ __launch_bounds__(256) void k_aggcsr(int N) {
    int node = blockIdx.x * 8 + (threadIdx.x >> 5);
    if (node >= N) return;
    int lane = threadIdx.x & 31;
    int start = g_off[node];
    int deg = g_ideg[node];
    float a0 = 0.f, a1 = 0.f, a2 = 0.f, a3 = 0.f;
    int j = 0;
    for (; j + 2 <= deg; j += 2) {
        int s0 = __ldg(&g_elist[start + j]);
        int s1 = __ldg(&g_elist[start + j + 1]);
        float c0 = __ldg(&g_csrc[s0]);
        float c1 = __ldg(&g_csrc[s1]);
        uint2 u0 = __ldg((const uint2*)(g_xh + (size_t)s0 * D) + lane);
        uint2 u1 = __ldg((const uint2*)(g_xh + (size_t)s1 * D) + lane);
        float2 p;
        p = __half22float2(*(__half2*)&u0.x); a0 += p.x * c0; a1 += p.y * c0;
        p = __half22float2(*(__half2*)&u0.y); a2 += p.x * c0; a3 += p.y * c0;
        p = __half22float2(*(__half2*)&u1.x); a0 += p.x * c1; a1 += p.y * c1;
        p = __half22float2(*(__half2*)&u1.y); a2 += p.x * c1; a3 += p.y * c1;
    }
    if (j < deg) {
        int s0 = __ldg(&g_elist[start + j]);
        float c0 = __ldg(&g_csrc[s0]);
        uint2 u0 = __ldg((const uint2*)(g_xh + (size_t)s0 * D) + lane);
        float2 p;
        p = __half22float2(*(__half2*)&u0.x); a0 += p.x * c0; a1 += p.y * c0;
        p = __half22float2(*(__half2*)&u0.y); a2 += p.x * c0; a3 += p.y * c0;
    }
    uint2 o;
    o.x = h2u(__floats2half2_rn(a0, a1));
    o.y = h2u(__floats2half2_rn(a2, a3));
    ((uint2*)(g_aggh + (size_t)node * D))[lane] = o;
}

// ---------------- fp16 tensor-core fused dual GEMM ---------------------------
#define MMA_F16(d, a, b0_, b1_) \
    asm volatile("mma.sync.aligned.m16n8k16.row.col.f32.f16.f16.f32 " \
        "{%0,%1,%2,%3},{%4,%5,%6,%7},{%8,%9},{%0,%1,%2,%3};" \
        : "+f"(d[0]), "+f"(d[1]), "+f"(d[2]), "+f"(d[3]) \
        : "r"(a[0]), "r"(a[1]), "r"(a[2]), "r"(a[3]), "r"(b0_), "r"(b1_))

// one 64-row fp16 tile stage via cp.async (16B chunks, swizzled)
__device__ __forceinline__ void stage_load(unsigned* buf, const __half* __restrict__ srcb,
                                           int row0, int N, int tid) {
#pragma unroll
    for (int i = 0; i < 4; i++) {
        int idx = tid + i * 256;
        int row = idx >> 4, kq = idx & 15;
        int grow = row0 + row;
        unsigned daddr = (unsigned)__cvta_generic_to_shared(
            buf + row * 64 + ((kq * 4) ^ ((row & 7) * 4)));
        const uint4* s = (const uint4*)(srcb + (size_t)(grow < N ? grow : 0) * D) + kq;
        int sz = grow < N ? 16 : 0;
        asm volatile("cp.async.cg.shared.global [%0], [%1], 16, %2;"
                     :: "r"(daddr), "l"(s), "r"(sz));
    }
}

// MMA over one branch for the current 64-row fp16 stage. Warp tile m32 x n32.
#define MMA_STAGE(ACC, BR)                                                         \
    _Pragma("unroll")                                                              \
    for (int jp = 0; jp < 8; jp++) {                                               \
        unsigned a[2][4];                                                          \
        int w0 = jp * 8 + tig;                                                     \
        _Pragma("unroll")                                                          \
        for (int mf = 0; mf < 2; mf++) {                                           \
            int row = mw * 32 + mf * 16 + gid;                                     \
            a[mf][0] = asb[row * 64 + (w0 ^ (gid * 4))];                           \
            a[mf][1] = asb[(row + 8) * 64 + (w0 ^ (gid * 4))];                     \
            a[mf][2] = asb[row * 64 + ((w0 + 4) ^ (gid * 4))];                     \
            a[mf][3] = asb[(row + 8) * 64 + ((w0 + 4) ^ (gid * 4))];               \
        }                                                                          \
        _Pragma("unroll")                                                          \
        for (int t = 0; t < 4; t++) {                                              \
            uint2 bf = ws2[(((nw * 2 + (BR)) * 4 + t) << 8) + jp * 32 + lane];     \
            MMA_F16(ACC[0][t], a[0], bf.x, bf.y);                                  \
            MMA_F16(ACC[1][t], a[1], bf.x, bf.y);                                  \
        }                                                                          \
    }

// Block: 256 thr = 8 warps = 2(m) x 4(n); warp tile m32 x n32, both branches.
// 2 blocks/SM. Weights pre-packed in global, copied via cp.async (no prologue).
// smem: ws 64KB + 2 x 16KB fp16 A stages + 1KB biases = 97KB per block.
__global__ __launch_bounds__(256, 2) void k_gemm_fp16(
    const float* __restrict__ bb, const float* __restrict__ brr,
    int N, int numTiles)
{
    extern __shared__ unsigned smem_u[];
    unsigned* ws  = smem_u;           // 16384 words = 64KB
    unsigned* as0 = smem_u + 16384;   //  4096 words = 16KB (64 rows fp16)
    unsigned* as1 = smem_u + 20480;   //  4096 words = 16KB
    float* bsm    = (float*)(smem_u + 24576);   // 128 floats
    float* qsm    = bsm + 128;                  // 128 floats
    const uint2* ws2 = (const uint2*)ws;

    const int tid  = threadIdx.x;
    const int lane = tid & 31;
    const int wid  = tid >> 5;
    const int mw   = wid >> 2;     // 0..1 (m group of 32 rows)
    const int nw   = wid & 3;      // 0..3 (n group of 32 cols)
    const int tig  = lane & 3;
    const int gid  = lane >> 2;

    if (tid < 128) { bsm[tid] = __ldg(&bb[tid]); qsm[tid] = __ldg(&brr[tid]); }

    // weights: flat 64KB cp.async copy from pre-packed global
#pragma unroll
    for (int i = 0; i < 16; i++) {
        int idx = tid + i * 256;    // uint4 index, 4096 total
        unsigned daddr = (unsigned)__cvta_generic_to_shared(ws + idx * 4);
        asm volatile("cp.async.cg.shared.global [%0], [%1], 16;"
                     :: "r"(daddr), "l"(((const uint4*)g_wsp) + idx));
    }
    // prologue stage 0 (agg of tile0) shares the first commit group with ws
    stage_load(as0, g_aggh, blockIdx.x * BM, N, tid);
    asm volatile("cp.async.commit_group;");
    stage_load(as1, g_xh, blockIdx.x * BM, N, tid);
    asm volatile("cp.async.commit_group;");

    float ts[8], tq[8];
#pragma unroll
    for (int i = 0; i < 8; i++) { ts[i] = 0.f; tq[i] = 0.f; }

    const int nT = (numTiles > (int)blockIdx.x)
                 ? (numTiles - blockIdx.x + gridDim.x - 1) / gridDim.x : 0;
    const int totalS = nT * 2;

    float acc0[2][4][4], acc1[2][4][4];

    for (int s = 0; s < totalS; s++) {
        const int br   = s & 1;
        const int tile = blockIdx.x + (s >> 1) * gridDim.x;
        const int row0 = tile * BM;

        asm volatile("cp.async.wait_group 1;");
        __syncthreads();
        const unsigned* asb = br ? as1 : as0;

        if (br == 0) {
#pragma unroll
            for (int mf = 0; mf < 2; mf++)
#pragma unroll
                for (int t = 0; t < 4; t++)
#pragma unroll
                    for (int r = 0; r < 4; r++) { acc0[mf][t][r] = 0.f; acc1[mf][t][r] = 0.f; }
            MMA_STAGE(acc0, 0)
        } else {
            MMA_STAGE(acc1, 1)
        }

        __syncthreads();  // all reads of asb done before overwrite

        int s2 = s + 2;
        if (s2 < totalS) {
            int t2 = blockIdx.x + (s2 >> 1) * gridDim.x;
            stage_load((s2 & 1) ? as1 : as0, (s2 & 1) ? g_xh : g_aggh, t2 * BM, N, tid);
        }
        asm volatile("cp.async.commit_group;");

        if (br == 1) {
            // epilogue: y = relu(h*cd + b) + relu(res + q), write fp16 y, BN sums
#pragma unroll
            for (int mf = 0; mf < 2; mf++) {
                int rA = row0 + mw * 32 + mf * 16 + gid;
                int rB = rA + 8;
                float cdA = (rA < N) ? __ldg(&g_cdst[rA]) : 0.f;
                float cdB = (rB < N) ? __ldg(&g_cdst[rB]) : 0.f;
#pragma unroll
                for (int t = 0; t < 4; t++) {
                    int col = nw * 32 + t * 8 + 2 * tig;
                    float2 b2 = *(float2*)&bsm[col];
                    float2 q2 = *(float2*)&qsm[col];
                    if (rA < N) {
                        float v0 = fmaxf(acc0[mf][t][0] * cdA + b2.x, 0.f)
                                 + fmaxf(acc1[mf][t][0] + q2.x, 0.f);
                        float v1 = fmaxf(acc0[mf][t][1] * cdA + b2.y, 0.f)
                                 + fmaxf(acc1[mf][t][1] + q2.y, 0.f);
                        *(__half2*)&g_yh[(size_t)rA * D + col] = __floats2half2_rn(v0, v1);
                        ts[2 * t] += v0; tq[2 * t] += v0 * v0;
                        ts[2 * t + 1] += v1; tq[2 * t + 1] += v1 * v1;
                    }
                    if (rB < N) {
                        float v2 = fmaxf(acc0[mf][t][2] * cdB + b2.x, 0.f)
                                 + fmaxf(acc1[mf][t][2] + q2.x, 0.f);
                        float v3 = fmaxf(acc0[mf][t][3] * cdB + b2.y, 0.f)
                                 + fmaxf(acc1[mf][t][3] + q2.y, 0.f);
                        *(__half2*)&g_yh[(size_t)rB * D + col] = __floats2half2_rn(v2, v3);
                        ts[2 * t] += v2; tq[2 * t] += v2 * v2;
                        ts[2 * t + 1] += v3; tq[2 * t + 1] += v3 * v3;
                    }
                }
            }
        }
    }

    // ---- BN sums: lanes gid 0..7 hold identical column sets -> reduce ----
#pragma unroll
    for (int i = 0; i < 8; i++) {
#pragma unroll
        for (int m = 4; m <= 16; m <<= 1) {
            ts[i] += __shfl_xor_sync(0xffffffffu, ts[i], m);
            tq[i] += __shfl_xor_sync(0xffffffffu, tq[i], m);
        }
    }
    if (gid == 0) {
#pragma unroll
        for (int i = 0; i < 8; i++) {
            int col = nw * 32 + (i >> 1) * 8 + 2 * tig + (i & 1);
            atomicAdd(&g_colsum[col], ts[i]);
            atomicAdd(&g_colsq[col], tq[i]);
        }
    }
}

// ---------------- BN parameter fold + apply ----------------------------------
__global__ void k_bnparams(const float* __restrict__ gamma, const float* __restrict__ beta, float invN) {
    int j = threadIdx.x;
    float mean = g_colsum[j] * invN;
    float var = fmaxf(g_colsq[j] * invN - mean * mean, 0.f);
    float s = rsqrtf(var + BN_EPS) * __ldg(&gamma[j]);
    g_scale[j] = s;
    g_shift[j] = __ldg(&beta[j]) - mean * s;
}

// reads fp16 y (8 halves per thread), writes fp32 out
__global__ __launch_bounds__(256) void k_bnapply(float4* __restrict__ out4, int chunks) {
    int i = blockIdx.x * blockDim.x + threadIdx.x;
    if (i >= chunks) return;
    uint4 u = ((const uint4*)g_yh)[i];
    int c0 = (i & 15) * 8;
    float4 o0, o1;
    float2 p;
    p = __half22float2(*(__half2*)&u.x);
    o0.x = p.x * g_scale[c0    ] + g_shift[c0    ];
    o0.y = p.y * g_scale[c0 + 1] + g_shift[c0 + 1];
    p = __half22float2(*(__half2*)&u.y);
    o0.z = p.x * g_scale[c0 + 2] + g_shift[c0 + 2];
    o0.w = p.y * g_scale[c0 + 3] + g_shift[c0 + 3];
    p = __half22float2(*(__half2*)&u.z);
    o1.x = p.x * g_scale[c0 + 4] + g_shift[c0 + 4];
    o1.y = p.y * g_scale[c0 + 5] + g_shift[c0 + 5];
    p = __half22float2(*(__half2*)&u.w);
    o1.z = p.x * g_scale[c0 + 6] + g_shift[c0 + 6];
    o1.w = p.y * g_scale[c0 + 7] + g_shift[c0 + 7];
    out4[2 * i]     = o0;
    out4[2 * i + 1] = o1;
}

// ---------------- launch ------------------------------------------------------
extern "C" void kernel_launch(void* const* d_in, const int* in_sizes, int n_in,
                              void* d_out, int out_size) {
    const float* x     = (const float*)d_in[0];
    const float* W     = (const float*)d_in[1];
    const float* b     = (const float*)d_in[2];
    const float* Wr    = (const float*)d_in[3];
    const float* br    = (const float*)d_in[4];
    const float* gamma = (const float*)d_in[5];
    const float* beta  = (const float*)d_in[6];
    const int*   src   = (const int*)d_in[7];
    const int*   dst   = (const int*)d_in[8];

    const int N = in_sizes[0] / D;
    const int E = in_sizes[7];

    void *p_odeg, *p_ideg, *p_ecnt;
    cudaGetSymbolAddress(&p_odeg, g_odeg);
    cudaGetSymbolAddress(&p_ideg, g_ideg);
    cudaGetSymbolAddress(&p_ecnt, g_ecnt);

    cudaMemsetAsync(p_odeg, 0, (size_t)N * sizeof(int));
    cudaMemsetAsync(p_ideg, 0, (size_t)N * sizeof(int));
    cudaMemsetAsync(p_ecnt, 0, sizeof(int));

    {
        int xChunks = N * (D / 8);
        int xBlocks = (xChunks + 255) / 256;
        int eBlocks = (E + 255) / 256;
        int wBlocks = 32;   // 8192 cells / 256
        k_prep<<<xBlocks + eBlocks + wBlocks, 256>>>(src, dst, E, (const float4*)x,
                                                     xChunks, xBlocks, eBlocks, W, Wr);
    }
    k_cnorm<<<(N + 255) / 256, 256>>>(N);
    k_offsets<<<(N + 255) / 256, 256>>>(N);
    k_binedges<<<(E + 255) / 256, 256>>>(src, dst, E);
    k_aggcsr<<<(N + 7) / 8, 256>>>(N);

    {
        const int smemBytes = 24832 * (int)sizeof(unsigned);  // 97 KB
        cudaFuncSetAttribute(k_gemm_fp16, cudaFuncAttributeMaxDynamicSharedMemorySize, smemBytes);
        int numTiles = (N + BM - 1) / BM;
        int grid = numTiles < 304 ? numTiles : 304;   // 2 blocks per SM
        k_gemm_fp16<<<grid, 256, smemBytes>>>(b, br, N, numTiles);
    }

    k_bnparams<<<1, D>>>(gamma, beta, 1.0f / (float)N);
    {
        int chunks = N * (D / 8);
        k_bnapply<<<(chunks + 255) / 256, 256>>>((float4*)d_out, chunks);
    }
}